// round 4
// baseline (speedup 1.0000x reference)
#include <cuda_runtime.h>
#include <cuda_bf16.h>
#include <float.h>

// ---------------------------------------------------------------------------
// Single fused kernel: per-block redundant weight-scale computation +
// MaxPool3d(2) + int4-dequant linear(2048->4) + bias + softmax.
//
// Scale phase: W is [4,2048] = 32KB, L2-resident after wave 1. Each of the
// 256 threads loads 8 float4 (covers all 2048 float4), block max-reduce gives
// scale = max|W|/7 identically in every block.
//
// Main phase (2 batch rows per block): each thread handles 4 feature-PAIRS
// per row via 4 coalesced float4 loads per pair-pair (evict-first, pure
// streaming). Weights are loaded as float2 (L1/L2 hit) and dequantized
// inline: q = rint(w/s)*s  (clip(-8,7) never binds since |w|/s <= 7).
//
// x layout: [B, C=4, D=16, H=16, W=16] f32, 16384 floats per row.
// pair index fp in [0,1024): c = fp>>8, rem = fp&255,
//   pd = rem>>5, ph = (rem>>2)&7, pwp = rem&3
// base float offset = c*4096 + pd*512 + ph*32 + pwp*4
// ---------------------------------------------------------------------------
__global__ void __launch_bounds__(256)
fused_all_kernel(const float* __restrict__ x,
                 const float* __restrict__ W,
                 const float* __restrict__ bias,
                 float* __restrict__ out) {
    __shared__ float s_warp[8];
    __shared__ float s_scale;
    __shared__ float s_red[8][8];   // [warp][row0 accs 0..3 | row1 accs 4..7]

    const int b0 = blockIdx.x * 2;
    const int t = threadIdx.x;
    const int wid = t >> 5;
    const float* __restrict__ xb0 = x + (size_t)b0 * 16384;
    const float* __restrict__ xb1 = xb0 + 16384;

    // ---- Phase 1: block-wide max|W| -> scale (identical in every block) ----
    const float4* __restrict__ W4 = reinterpret_cast<const float4*>(W);
    float m = 0.0f;
    #pragma unroll
    for (int k = 0; k < 8; k++) {
        const float4 w = __ldg(&W4[t + k * 256]);
        m = fmaxf(m, fmaxf(fmaxf(fabsf(w.x), fabsf(w.y)),
                           fmaxf(fabsf(w.z), fabsf(w.w))));
    }
    #pragma unroll
    for (int off = 16; off > 0; off >>= 1)
        m = fmaxf(m, __shfl_xor_sync(0xFFFFFFFFu, m, off));
    if ((t & 31) == 0) s_warp[wid] = m;
    __syncthreads();
    if (t == 0) {
        float mm = s_warp[0];
        #pragma unroll
        for (int w = 1; w < 8; w++) mm = fmaxf(mm, s_warp[w]);
        s_scale = mm / 7.0f;
    }
    __syncthreads();
    const float scale = s_scale;
    const float inv_scale = 1.0f / scale;

    // Preload bias early (uniform broadcast).
    const float4 bias4 = *reinterpret_cast<const float4*>(bias);

    // ---- Phase 2: streaming pool + dequant-GEMV ----
    float p0 = 0.0f, p1 = 0.0f, p2 = 0.0f, p3 = 0.0f;   // row 0 partials
    float q0 = 0.0f, q1 = 0.0f, q2 = 0.0f, q3 = 0.0f;   // row 1 partials

    #pragma unroll
    for (int k = 0; k < 4; k++) {
        const int fp  = t + k * 256;
        const int c   = fp >> 8;
        const int rem = fp & 255;
        const int pd  = rem >> 5;
        const int ph  = (rem >> 2) & 7;
        const int pwp = rem & 3;
        const int off = c * 4096 + pd * 512 + ph * 32 + pwp * 4;

        const float4* pa = reinterpret_cast<const float4*>(xb0 + off);
        const float4* pb = reinterpret_cast<const float4*>(xb1 + off);

        const float4 a0 = __ldcs(pa);        // (d0, h0)
        const float4 a1 = __ldcs(pa + 4);    // (d0, h1)
        const float4 a2 = __ldcs(pa + 64);   // (d1, h0)
        const float4 a3 = __ldcs(pa + 68);   // (d1, h1)
        const float4 c0 = __ldcs(pb);
        const float4 c1 = __ldcs(pb + 4);
        const float4 c2 = __ldcs(pb + 64);
        const float4 c3 = __ldcs(pb + 68);

        const float ma0 = fmaxf(fmaxf(fmaxf(a0.x, a0.y), fmaxf(a1.x, a1.y)),
                                fmaxf(fmaxf(a2.x, a2.y), fmaxf(a3.x, a3.y)));
        const float ma1 = fmaxf(fmaxf(fmaxf(a0.z, a0.w), fmaxf(a1.z, a1.w)),
                                fmaxf(fmaxf(a2.z, a2.w), fmaxf(a3.z, a3.w)));
        const float mb0 = fmaxf(fmaxf(fmaxf(c0.x, c0.y), fmaxf(c1.x, c1.y)),
                                fmaxf(fmaxf(c2.x, c2.y), fmaxf(c3.x, c3.y)));
        const float mb1 = fmaxf(fmaxf(fmaxf(c0.z, c0.w), fmaxf(c1.z, c1.w)),
                                fmaxf(fmaxf(c2.z, c2.w), fmaxf(c3.z, c3.w)));

        const int f2 = fp * 2;
        float2 w0 = *reinterpret_cast<const float2*>(&W[f2]);
        float2 w1 = *reinterpret_cast<const float2*>(&W[2048 + f2]);
        float2 w2 = *reinterpret_cast<const float2*>(&W[4096 + f2]);
        float2 w3 = *reinterpret_cast<const float2*>(&W[6144 + f2]);

        // inline int4 dequant (half-to-even round; clip never binds)
        w0.x = rintf(w0.x * inv_scale) * scale;
        w0.y = rintf(w0.y * inv_scale) * scale;
        w1.x = rintf(w1.x * inv_scale) * scale;
        w1.y = rintf(w1.y * inv_scale) * scale;
        w2.x = rintf(w2.x * inv_scale) * scale;
        w2.y = rintf(w2.y * inv_scale) * scale;
        w3.x = rintf(w3.x * inv_scale) * scale;
        w3.y = rintf(w3.y * inv_scale) * scale;

        p0 = fmaf(ma0, w0.x, fmaf(ma1, w0.y, p0));
        p1 = fmaf(ma0, w1.x, fmaf(ma1, w1.y, p1));
        p2 = fmaf(ma0, w2.x, fmaf(ma1, w2.y, p2));
        p3 = fmaf(ma0, w3.x, fmaf(ma1, w3.y, p3));
        q0 = fmaf(mb0, w0.x, fmaf(mb1, w0.y, q0));
        q1 = fmaf(mb0, w1.x, fmaf(mb1, w1.y, q1));
        q2 = fmaf(mb0, w2.x, fmaf(mb1, w2.y, q2));
        q3 = fmaf(mb0, w3.x, fmaf(mb1, w3.y, q3));
    }

    // warp reduce all 8 accumulators
    #pragma unroll
    for (int off = 16; off > 0; off >>= 1) {
        p0 += __shfl_xor_sync(0xFFFFFFFFu, p0, off);
        p1 += __shfl_xor_sync(0xFFFFFFFFu, p1, off);
        p2 += __shfl_xor_sync(0xFFFFFFFFu, p2, off);
        p3 += __shfl_xor_sync(0xFFFFFFFFu, p3, off);
        q0 += __shfl_xor_sync(0xFFFFFFFFu, q0, off);
        q1 += __shfl_xor_sync(0xFFFFFFFFu, q1, off);
        q2 += __shfl_xor_sync(0xFFFFFFFFu, q2, off);
        q3 += __shfl_xor_sync(0xFFFFFFFFu, q3, off);
    }
    if ((t & 31) == 0) {
        s_red[wid][0] = p0;  s_red[wid][1] = p1;
        s_red[wid][2] = p2;  s_red[wid][3] = p3;
        s_red[wid][4] = q0;  s_red[wid][5] = q1;
        s_red[wid][6] = q2;  s_red[wid][7] = q3;
    }
    __syncthreads();

    // threads 0 and 1 each finish one row
    if (t < 2) {
        const int base = t * 4;
        float l0 = bias4.x, l1 = bias4.y, l2 = bias4.z, l3 = bias4.w;
        #pragma unroll
        for (int w = 0; w < 8; w++) {
            l0 += s_red[w][base + 0];
            l1 += s_red[w][base + 1];
            l2 += s_red[w][base + 2];
            l3 += s_red[w][base + 3];
        }
        const float mx = fmaxf(fmaxf(l0, l1), fmaxf(l2, l3));
        const float e0 = __expf(l0 - mx);
        const float e1 = __expf(l1 - mx);
        const float e2 = __expf(l2 - mx);
        const float e3 = __expf(l3 - mx);
        const float inv = 1.0f / (e0 + e1 + e2 + e3);
        float4 r = make_float4(e0 * inv, e1 * inv, e2 * inv, e3 * inv);
        *reinterpret_cast<float4*>(out + (size_t)(b0 + t) * 4) = r;
    }
}

extern "C" void kernel_launch(void* const* d_in, const int* in_sizes, int n_in,
                              void* d_out, int out_size) {
    const float* x = (const float*)d_in[0];   // [8192,4,16,16,16]
    const float* W = (const float*)d_in[1];   // [4,2048]
    const float* b = (const float*)d_in[2];   // [4]
    float* out = (float*)d_out;               // [8192,4]

    fused_all_kernel<<<4096, 256>>>(x, W, b, out);
}

// round 5
// speedup vs baseline: 1.0547x; 1.0547x over previous
#include <cuda_runtime.h>
#include <cuda_bf16.h>
#include <float.h>

// Dequantized int4 weights, [4][2048] row-major (output-major).
__device__ float g_Wq[4 * 2048];

// ---------------------------------------------------------------------------
// Kernel 1: per-tensor symmetric int4 quantize-dequantize of W [4,2048].
// scale = max|W| / 7 ; Wq = clip(rint(W/scale), -8, 7) * scale
// Single block, 256 threads, fully float4-vectorized (8 LDG.128 + 8 STG.128
// per thread), one warp-level + smem reduction.
// ---------------------------------------------------------------------------
__global__ void __launch_bounds__(256)
quantize_w_kernel(const float* __restrict__ W) {
    __shared__ float s_warp[8];
    __shared__ float s_scale;
    const int t = threadIdx.x;

    const float4* __restrict__ W4 = reinterpret_cast<const float4*>(W);
    float4 w[8];
    float m = 0.0f;
    #pragma unroll
    for (int k = 0; k < 8; k++) {
        w[k] = W4[t + k * 256];
        m = fmaxf(m, fmaxf(fmaxf(fabsf(w[k].x), fabsf(w[k].y)),
                           fmaxf(fabsf(w[k].z), fabsf(w[k].w))));
    }
    #pragma unroll
    for (int off = 16; off > 0; off >>= 1)
        m = fmaxf(m, __shfl_xor_sync(0xFFFFFFFFu, m, off));
    if ((t & 31) == 0) s_warp[t >> 5] = m;
    __syncthreads();
    if (t == 0) {
        float mm = fmaxf(fmaxf(fmaxf(s_warp[0], s_warp[1]),
                               fmaxf(s_warp[2], s_warp[3])),
                         fmaxf(fmaxf(s_warp[4], s_warp[5]),
                               fmaxf(s_warp[6], s_warp[7])));
        s_scale = mm / 7.0f;
    }
    __syncthreads();
    const float scale = s_scale;
    const float inv_scale = 1.0f / scale;

    float4* __restrict__ Wq4 = reinterpret_cast<float4*>(g_Wq);
    #pragma unroll
    for (int k = 0; k < 8; k++) {
        float4 r;                               // half-to-even, matches jnp.round
        r.x = rintf(w[k].x * inv_scale) * scale; // clip(-8,7) never binds: |w|/s <= 7
        r.y = rintf(w[k].y * inv_scale) * scale;
        r.z = rintf(w[k].z * inv_scale) * scale;
        r.w = rintf(w[k].w * inv_scale) * scale;
        Wq4[t + k * 256] = r;
    }
}

// ---------------------------------------------------------------------------
// Kernel 2: fused MaxPool3d(2) + linear(2048->4, Wq) + bias + softmax.
// TWO batch rows per block (256 threads). Each thread handles 4 feature-PAIRS
// per row (8 pooled features), via 4 coalesced float4 loads per pair-pair.
// The two rows share identical Wq float2 loads and their global loads
// interleave for deep MLP. (R3 main kernel: measured 81.2us, 84% DRAM.)
//
// x layout: [B, C=4, D=16, H=16, W=16] f32, 16384 floats per row.
// pair index fp in [0,1024): c = fp>>8, rem = fp&255,
//   pd = rem>>5, ph = (rem>>2)&7, pwp = rem&3
// base float offset = c*4096 + pd*512 + ph*32 + pwp*4
// ---------------------------------------------------------------------------
__global__ void __launch_bounds__(256)
fused_pool_linear_softmax_kernel(const float* __restrict__ x,
                                 const float* __restrict__ bias,
                                 float* __restrict__ out) {
    __shared__ float s_red[8][8];   // [warp][row0 accs 0..3 | row1 accs 4..7]

    const int b0 = blockIdx.x * 2;
    const int t = threadIdx.x;
    const float* __restrict__ xb0 = x + (size_t)b0 * 16384;
    const float* __restrict__ xb1 = xb0 + 16384;

    const float4 bias4 = *reinterpret_cast<const float4*>(bias);

    float p0 = 0.0f, p1 = 0.0f, p2 = 0.0f, p3 = 0.0f;   // row 0 partials
    float q0 = 0.0f, q1 = 0.0f, q2 = 0.0f, q3 = 0.0f;   // row 1 partials

    #pragma unroll
    for (int k = 0; k < 4; k++) {
        const int fp  = t + k * 256;
        const int c   = fp >> 8;
        const int rem = fp & 255;
        const int pd  = rem >> 5;
        const int ph  = (rem >> 2) & 7;
        const int pwp = rem & 3;
        const int off = c * 4096 + pd * 512 + ph * 32 + pwp * 4;

        const float4* pa = reinterpret_cast<const float4*>(xb0 + off);
        const float4* pb = reinterpret_cast<const float4*>(xb1 + off);

        const float4 a0 = __ldcs(pa);        // (d0, h0)
        const float4 a1 = __ldcs(pa + 4);    // (d0, h1)
        const float4 a2 = __ldcs(pa + 64);   // (d1, h0)
        const float4 a3 = __ldcs(pa + 68);   // (d1, h1)
        const float4 c0 = __ldcs(pb);
        const float4 c1 = __ldcs(pb + 4);
        const float4 c2 = __ldcs(pb + 64);
        const float4 c3 = __ldcs(pb + 68);

        const float ma0 = fmaxf(fmaxf(fmaxf(a0.x, a0.y), fmaxf(a1.x, a1.y)),
                                fmaxf(fmaxf(a2.x, a2.y), fmaxf(a3.x, a3.y)));
        const float ma1 = fmaxf(fmaxf(fmaxf(a0.z, a0.w), fmaxf(a1.z, a1.w)),
                                fmaxf(fmaxf(a2.z, a2.w), fmaxf(a3.z, a3.w)));
        const float mb0 = fmaxf(fmaxf(fmaxf(c0.x, c0.y), fmaxf(c1.x, c1.y)),
                                fmaxf(fmaxf(c2.x, c2.y), fmaxf(c3.x, c3.y)));
        const float mb1 = fmaxf(fmaxf(fmaxf(c0.z, c0.w), fmaxf(c1.z, c1.w)),
                                fmaxf(fmaxf(c2.z, c2.w), fmaxf(c3.z, c3.w)));

        const int f2 = fp * 2;
        const float2 w0 = *reinterpret_cast<const float2*>(&g_Wq[f2]);
        const float2 w1 = *reinterpret_cast<const float2*>(&g_Wq[2048 + f2]);
        const float2 w2 = *reinterpret_cast<const float2*>(&g_Wq[4096 + f2]);
        const float2 w3 = *reinterpret_cast<const float2*>(&g_Wq[6144 + f2]);

        p0 = fmaf(ma0, w0.x, fmaf(ma1, w0.y, p0));
        p1 = fmaf(ma0, w1.x, fmaf(ma1, w1.y, p1));
        p2 = fmaf(ma0, w2.x, fmaf(ma1, w2.y, p2));
        p3 = fmaf(ma0, w3.x, fmaf(ma1, w3.y, p3));
        q0 = fmaf(mb0, w0.x, fmaf(mb1, w0.y, q0));
        q1 = fmaf(mb0, w1.x, fmaf(mb1, w1.y, q1));
        q2 = fmaf(mb0, w2.x, fmaf(mb1, w2.y, q2));
        q3 = fmaf(mb0, w3.x, fmaf(mb1, w3.y, q3));
    }

    // warp reduce all 8 accumulators
    #pragma unroll
    for (int off = 16; off > 0; off >>= 1) {
        p0 += __shfl_xor_sync(0xFFFFFFFFu, p0, off);
        p1 += __shfl_xor_sync(0xFFFFFFFFu, p1, off);
        p2 += __shfl_xor_sync(0xFFFFFFFFu, p2, off);
        p3 += __shfl_xor_sync(0xFFFFFFFFu, p3, off);
        q0 += __shfl_xor_sync(0xFFFFFFFFu, q0, off);
        q1 += __shfl_xor_sync(0xFFFFFFFFu, q1, off);
        q2 += __shfl_xor_sync(0xFFFFFFFFu, q2, off);
        q3 += __shfl_xor_sync(0xFFFFFFFFu, q3, off);
    }
    const int wid = t >> 5;
    if ((t & 31) == 0) {
        s_red[wid][0] = p0;  s_red[wid][1] = p1;
        s_red[wid][2] = p2;  s_red[wid][3] = p3;
        s_red[wid][4] = q0;  s_red[wid][5] = q1;
        s_red[wid][6] = q2;  s_red[wid][7] = q3;
    }
    __syncthreads();

    // threads 0 and 1 each finish one row
    if (t < 2) {
        const int base = t * 4;
        float l0 = bias4.x, l1 = bias4.y, l2 = bias4.z, l3 = bias4.w;
        #pragma unroll
        for (int w = 0; w < 8; w++) {
            l0 += s_red[w][base + 0];
            l1 += s_red[w][base + 1];
            l2 += s_red[w][base + 2];
            l3 += s_red[w][base + 3];
        }
        const float mx = fmaxf(fmaxf(l0, l1), fmaxf(l2, l3));
        const float e0 = __expf(l0 - mx);
        const float e1 = __expf(l1 - mx);
        const float e2 = __expf(l2 - mx);
        const float e3 = __expf(l3 - mx);
        const float inv = 1.0f / (e0 + e1 + e2 + e3);
        float4 r = make_float4(e0 * inv, e1 * inv, e2 * inv, e3 * inv);
        *reinterpret_cast<float4*>(out + (size_t)(b0 + t) * 4) = r;
    }
}

extern "C" void kernel_launch(void* const* d_in, const int* in_sizes, int n_in,
                              void* d_out, int out_size) {
    const float* x = (const float*)d_in[0];   // [8192,4,16,16,16]
    const float* W = (const float*)d_in[1];   // [4,2048]
    const float* b = (const float*)d_in[2];   // [4]
    float* out = (float*)d_out;               // [8192,4]

    quantize_w_kernel<<<1, 256>>>(W);
    fused_pool_linear_softmax_kernel<<<4096, 256>>>(x, b, out);
}

// round 6
// speedup vs baseline: 1.0784x; 1.0225x over previous
#include <cuda_runtime.h>
#include <cuda_bf16.h>
#include <float.h>

// {scale, 1/scale} computed by the prologue.
__device__ float2 g_scale2;

// ---------------------------------------------------------------------------
// Kernel 1: scale-only prologue. max|W| over [4,2048] -> scale = max/7.
// 1024 threads, 2 float4 loads each (covers all 2048 float4). Pure latency
// chain: ~1 DRAM round trip + shuffle tree + 8-byte store.
// ---------------------------------------------------------------------------
__global__ void __launch_bounds__(1024)
scale_kernel(const float* __restrict__ W) {
    __shared__ float s_warp[32];
    const int t = threadIdx.x;

    const float4* __restrict__ W4 = reinterpret_cast<const float4*>(W);
    const float4 a = W4[t];
    const float4 b = W4[t + 1024];
    float m = fmaxf(fmaxf(fmaxf(fabsf(a.x), fabsf(a.y)),
                          fmaxf(fabsf(a.z), fabsf(a.w))),
                    fmaxf(fmaxf(fabsf(b.x), fabsf(b.y)),
                          fmaxf(fabsf(b.z), fabsf(b.w))));
    #pragma unroll
    for (int off = 16; off > 0; off >>= 1)
        m = fmaxf(m, __shfl_xor_sync(0xFFFFFFFFu, m, off));
    if ((t & 31) == 0) s_warp[t >> 5] = m;
    __syncthreads();
    if (t == 0) {
        float mm = s_warp[0];
        #pragma unroll
        for (int w = 1; w < 32; w++) mm = fmaxf(mm, s_warp[w]);
        const float scale = mm / 7.0f;
        g_scale2 = make_float2(scale, 1.0f / scale);
    }
}

// ---------------------------------------------------------------------------
// Kernel 2: fused MaxPool3d(2) + inline int4-dequant linear(2048->4) + bias
// + softmax. TWO batch rows per block (256 threads), 4 feature-pairs per row
// per thread via coalesced float4 streaming loads (evict-first).
// Weights read raw from W (L2-resident) and dequantized inline:
//   wq = rint(w * inv_s) * s   (clip(-8,7) never binds: |w|/s <= 7)
// Only per-CTA preamble: one 8-byte broadcast load of {s, 1/s} (no barrier).
//
// x layout: [B, C=4, D=16, H=16, W=16] f32, 16384 floats per row.
// pair index fp in [0,1024): c = fp>>8, rem = fp&255,
//   pd = rem>>5, ph = (rem>>2)&7, pwp = rem&3
// base float offset = c*4096 + pd*512 + ph*32 + pwp*4
// ---------------------------------------------------------------------------
__global__ void __launch_bounds__(256)
fused_pool_linear_softmax_kernel(const float* __restrict__ x,
                                 const float* __restrict__ W,
                                 const float* __restrict__ bias,
                                 float* __restrict__ out) {
    __shared__ float s_red[8][8];   // [warp][row0 accs 0..3 | row1 accs 4..7]

    const int b0 = blockIdx.x * 2;
    const int t = threadIdx.x;
    const float* __restrict__ xb0 = x + (size_t)b0 * 16384;
    const float* __restrict__ xb1 = xb0 + 16384;

    // Issued immediately; consumed only at the first FMA hundreds of cycles
    // later. No barrier, no W sweep (the R4 mistake).
    const float2 sc = g_scale2;
    const float scale = sc.x, inv_scale = sc.y;
    const float4 bias4 = *reinterpret_cast<const float4*>(bias);

    float p0 = 0.0f, p1 = 0.0f, p2 = 0.0f, p3 = 0.0f;   // row 0 partials
    float q0 = 0.0f, q1 = 0.0f, q2 = 0.0f, q3 = 0.0f;   // row 1 partials

    #pragma unroll
    for (int k = 0; k < 4; k++) {
        const int fp  = t + k * 256;
        const int c   = fp >> 8;
        const int rem = fp & 255;
        const int pd  = rem >> 5;
        const int ph  = (rem >> 2) & 7;
        const int pwp = rem & 3;
        const int off = c * 4096 + pd * 512 + ph * 32 + pwp * 4;

        const float4* pa = reinterpret_cast<const float4*>(xb0 + off);
        const float4* pb = reinterpret_cast<const float4*>(xb1 + off);

        const float4 a0 = __ldcs(pa);        // (d0, h0)
        const float4 a1 = __ldcs(pa + 4);    // (d0, h1)
        const float4 a2 = __ldcs(pa + 64);   // (d1, h0)
        const float4 a3 = __ldcs(pa + 68);   // (d1, h1)
        const float4 c0 = __ldcs(pb);
        const float4 c1 = __ldcs(pb + 4);
        const float4 c2 = __ldcs(pb + 64);
        const float4 c3 = __ldcs(pb + 68);

        const float ma0 = fmaxf(fmaxf(fmaxf(a0.x, a0.y), fmaxf(a1.x, a1.y)),
                                fmaxf(fmaxf(a2.x, a2.y), fmaxf(a3.x, a3.y)));
        const float ma1 = fmaxf(fmaxf(fmaxf(a0.z, a0.w), fmaxf(a1.z, a1.w)),
                                fmaxf(fmaxf(a2.z, a2.w), fmaxf(a3.z, a3.w)));
        const float mb0 = fmaxf(fmaxf(fmaxf(c0.x, c0.y), fmaxf(c1.x, c1.y)),
                                fmaxf(fmaxf(c2.x, c2.y), fmaxf(c3.x, c3.y)));
        const float mb1 = fmaxf(fmaxf(fmaxf(c0.z, c0.w), fmaxf(c1.z, c1.w)),
                                fmaxf(fmaxf(c2.z, c2.w), fmaxf(c3.z, c3.w)));

        const int f2 = fp * 2;
        float2 w0 = *reinterpret_cast<const float2*>(&W[f2]);
        float2 w1 = *reinterpret_cast<const float2*>(&W[2048 + f2]);
        float2 w2 = *reinterpret_cast<const float2*>(&W[4096 + f2]);
        float2 w3 = *reinterpret_cast<const float2*>(&W[6144 + f2]);

        // inline int4 dequant (half-to-even; same reciprocal-multiply rounding
        // as all previous passing rounds)
        w0.x = rintf(w0.x * inv_scale) * scale;
        w0.y = rintf(w0.y * inv_scale) * scale;
        w1.x = rintf(w1.x * inv_scale) * scale;
        w1.y = rintf(w1.y * inv_scale) * scale;
        w2.x = rintf(w2.x * inv_scale) * scale;
        w2.y = rintf(w2.y * inv_scale) * scale;
        w3.x = rintf(w3.x * inv_scale) * scale;
        w3.y = rintf(w3.y * inv_scale) * scale;

        p0 = fmaf(ma0, w0.x, fmaf(ma1, w0.y, p0));
        p1 = fmaf(ma0, w1.x, fmaf(ma1, w1.y, p1));
        p2 = fmaf(ma0, w2.x, fmaf(ma1, w2.y, p2));
        p3 = fmaf(ma0, w3.x, fmaf(ma1, w3.y, p3));
        q0 = fmaf(mb0, w0.x, fmaf(mb1, w0.y, q0));
        q1 = fmaf(mb0, w1.x, fmaf(mb1, w1.y, q1));
        q2 = fmaf(mb0, w2.x, fmaf(mb1, w2.y, q2));
        q3 = fmaf(mb0, w3.x, fmaf(mb1, w3.y, q3));
    }

    // warp reduce all 8 accumulators
    #pragma unroll
    for (int off = 16; off > 0; off >>= 1) {
        p0 += __shfl_xor_sync(0xFFFFFFFFu, p0, off);
        p1 += __shfl_xor_sync(0xFFFFFFFFu, p1, off);
        p2 += __shfl_xor_sync(0xFFFFFFFFu, p2, off);
        p3 += __shfl_xor_sync(0xFFFFFFFFu, p3, off);
        q0 += __shfl_xor_sync(0xFFFFFFFFu, q0, off);
        q1 += __shfl_xor_sync(0xFFFFFFFFu, q1, off);
        q2 += __shfl_xor_sync(0xFFFFFFFFu, q2, off);
        q3 += __shfl_xor_sync(0xFFFFFFFFu, q3, off);
    }
    const int wid = t >> 5;
    if ((t & 31) == 0) {
        s_red[wid][0] = p0;  s_red[wid][1] = p1;
        s_red[wid][2] = p2;  s_red[wid][3] = p3;
        s_red[wid][4] = q0;  s_red[wid][5] = q1;
        s_red[wid][6] = q2;  s_red[wid][7] = q3;
    }
    __syncthreads();

    // threads 0 and 1 each finish one row
    if (t < 2) {
        const int base = t * 4;
        float l0 = bias4.x, l1 = bias4.y, l2 = bias4.z, l3 = bias4.w;
        #pragma unroll
        for (int w = 0; w < 8; w++) {
            l0 += s_red[w][base + 0];
            l1 += s_red[w][base + 1];
            l2 += s_red[w][base + 2];
            l3 += s_red[w][base + 3];
        }
        const float mx = fmaxf(fmaxf(l0, l1), fmaxf(l2, l3));
        const float e0 = __expf(l0 - mx);
        const float e1 = __expf(l1 - mx);
        const float e2 = __expf(l2 - mx);
        const float e3 = __expf(l3 - mx);
        const float inv = 1.0f / (e0 + e1 + e2 + e3);
        float4 r = make_float4(e0 * inv, e1 * inv, e2 * inv, e3 * inv);
        *reinterpret_cast<float4*>(out + (size_t)(b0 + t) * 4) = r;
    }
}

extern "C" void kernel_launch(void* const* d_in, const int* in_sizes, int n_in,
                              void* d_out, int out_size) {
    const float* x = (const float*)d_in[0];   // [8192,4,16,16,16]
    const float* W = (const float*)d_in[1];   // [4,2048]
    const float* b = (const float*)d_in[2];   // [4]
    float* out = (float*)d_out;               // [8192,4]

    scale_kernel<<<1, 1024>>>(W);
    fused_pool_linear_softmax_kernel<<<4096, 256>>>(x, W, b, out);
}